// round 7
// baseline (speedup 1.0000x reference)
#include <cuda_runtime.h>
#include <cstdint>

#define NQ   50000
#define MNB  32
#define NKP  15
#define DIN  64
#define DOUT 64
#define OD   45
#define ODP  48
#define KD   960
#define MT   128                      // GEMM M tile
#define GEMM_BLOCKS ((NQ + MT - 1)/MT) // 391
#define KC   32                       // GEMM k chunk
#define NCHK (KD/KC)                  // 30
#define RA   160                      // A_sm row stride (floats), swizzle-padded

// ---------------- global scratch (allowed: __device__ arrays) ----------------
__device__ float g_wf[NQ*KD];        // 192MB: WF1 then reused as WF2
__device__ float g_of[NQ*ODP];       // offset features (padded to 48)
__device__ float g_owpad[KD*ODP];    // zero-padded offset weights

__global__ void prep_owpad(const float* __restrict__ ow)
{
    int i = blockIdx.x*blockDim.x + threadIdx.x;
    if (i < KD*ODP) {
        int kk = i / ODP, e = i - kk*ODP;
        g_owpad[i] = (e < OD) ? ow[kk*OD + e] : 0.0f;
    }
}

__device__ __forceinline__ uint64_t ffma2(uint64_t a, uint64_t b, uint64_t c)
{
    uint64_t d;
    asm("fma.rn.f32x2 %0, %1, %2, %3;" : "=l"(d) : "l"(a), "l"(b), "l"(c));
    return d;
}
__device__ __forceinline__ uint64_t dup2(float v)
{
    uint64_t d;
    asm("mov.b64 %0, {%1, %1};" : "=l"(d) : "f"(v));
    return d;
}
__device__ __forceinline__ float lo32(uint64_t v) { return __uint_as_float((uint32_t)v); }
__device__ __forceinline__ float hi32(uint64_t v) { return __uint_as_float((uint32_t)(v >> 32)); }

// ======================= Aggregation kernels =======================
// One query per warp, 8 queries per block. Lane owns channel pair (2l,2l+1).
// DEFORM=false: kernel points = kpts.  DEFORM=true: kpts + g_of offsets.
template<bool DEFORM>
__global__ __launch_bounds__(256, 3)
void agg_kernel(
    const float* __restrict__ qp,
    const float* __restrict__ sp,
    const int*   __restrict__ neigh,
    const float* __restrict__ x,
    const float* __restrict__ kpts)
{
    __shared__ float s_kp[48];
    __shared__ float s_dk[8][48];
    __shared__ float s_aw[8][MNB*36];

    const int tid  = threadIdx.x;
    const int lane = tid & 31;
    const int warp = tid >> 5;
    const int q    = blockIdx.x * 8 + warp;

    if (tid < OD) s_kp[tid] = kpts[tid];
    __syncthreads();

    const float* kpp;
    if (DEFORM) {
        float* dk = s_dk[warp];
        if (lane < OD)      dk[lane]      = s_kp[lane]      + g_of[q*ODP + lane];
        if (lane + 32 < OD) dk[lane + 32] = s_kp[lane + 32] + g_of[q*ODP + lane + 32];
        __syncwarp();
        kpp = dk;
    } else {
        kpp = s_kp;
    }

    // geometry: lane = its own neighbor index m
    float qx = qp[q*3+0], qy = qp[q*3+1], qz = qp[q*3+2];
    int   ni = neigh[q*MNB + lane];
    float nbx = sp[ni*3+0] - qx;
    float nby = sp[ni*3+1] - qy;
    float nbz = sp[ni*3+2] - qz;

    // influence weights, duplicated (w,w), row stride 36 floats
    float* awr = s_aw[warp] + lane*36;
#pragma unroll
    for (int k = 0; k < NKP; k++) {
        float dx = nbx - kpp[3*k+0];
        float dy = nby - kpp[3*k+1];
        float dz = nbz - kpp[3*k+2];
        float d  = sqrtf(fmaf(dx, dx, fmaf(dy, dy, dz*dz)));
        float wv = fmaxf(1.0f - d, 0.0f);
        *(float2*)(awr + 2*k) = make_float2(wv, wv);
    }
    __syncwarp();

    uint64_t acc[NKP];
#pragma unroll
    for (int k = 0; k < NKP; k++) acc[k] = 0ull;

    const float* awb = s_aw[warp];

#pragma unroll 4
    for (int m = 0; m < MNB; m++) {
        int n = __shfl_sync(0xffffffffu, ni, m);
        uint64_t f2 = *(const uint64_t*)(x + n*DIN + 2*lane);
        const ulonglong2* ar = (const ulonglong2*)(awb + m*36);
        {
            ulonglong2 a0 = ar[0], a1 = ar[1], a2 = ar[2], a3 = ar[3];
            acc[0] = ffma2(a0.x, f2, acc[0]);
            acc[1] = ffma2(a0.y, f2, acc[1]);
            acc[2] = ffma2(a1.x, f2, acc[2]);
            acc[3] = ffma2(a1.y, f2, acc[3]);
            acc[4] = ffma2(a2.x, f2, acc[4]);
            acc[5] = ffma2(a2.y, f2, acc[5]);
            acc[6] = ffma2(a3.x, f2, acc[6]);
            acc[7] = ffma2(a3.y, f2, acc[7]);
        }
        {
            ulonglong2 a4 = ar[4], a5 = ar[5], a6 = ar[6], a7 = ar[7];
            acc[8]  = ffma2(a4.x, f2, acc[8]);
            acc[9]  = ffma2(a4.y, f2, acc[9]);
            acc[10] = ffma2(a5.x, f2, acc[10]);
            acc[11] = ffma2(a5.y, f2, acc[11]);
            acc[12] = ffma2(a6.x, f2, acc[12]);
            acc[13] = ffma2(a6.y, f2, acc[13]);
            acc[14] = ffma2(a7.x, f2, acc[14]);
        }
    }

    // coalesced STG.64: WF[q][k*64 + 2*lane]
    float* wr = g_wf + (size_t)q*KD;
#pragma unroll
    for (int k = 0; k < NKP; k++)
        *(uint64_t*)(wr + k*DIN + 2*lane) = acc[k];
}

// ======================= GEMM kernel =======================
// C[M=50000][NN] = g_wf[M][960] @ B[960][NN] (+ bias on first OD cols).
// M-tile 128, 256 threads. Thread (tx=tid&15 -> channel quad, ty=tid>>4 -> q octet).
// A staged transposed+swizzled: A_sm[kc][RA] with shift 4*((kc>>2)&7) -> conflict-free
// STS.32 transpose AND aligned q-vector LDS.128 reads (q-pairs packed for FFMA2).
template<int NN, bool BIAS>
__global__ __launch_bounds__(256, 3)
void gemm_kernel(const float* __restrict__ B,
                 const float* __restrict__ bias,
                 float*       __restrict__ C)
{
    constexpr int NQd = NN/4;        // channel quads
    constexpr int RB  = NN + 4;      // B_sm row stride (multiple of 4 floats)
    constexpr int ASZ = KC*RA;       // 5120 floats per A buffer
    constexpr int BSZ = KC*RB;       // per B buffer
    constexpr int BQUADS = KC*NQd;   // quads per B chunk

    extern __shared__ float sm[];
    float* A_sm = sm;                 // 2 * ASZ
    float* B_sm = sm + 2*ASZ;         // 2 * BSZ

    const int tid = threadIdx.x;
    const int tx  = tid & 15;
    const int ty  = tid >> 4;
    const int q0  = blockIdx.x * MT;
    // inactive channel quads for NN=48 read lane 0 instead (avoid OOB smem)
    const int txc = (NQd == 16) ? tx : (tx < NQd ? tx : 0);

    float4 pa[4];
    float4 pb[2];

    // ---- load chunk helper (into registers) ----
    auto load_chunk = [&](int c) {
#pragma unroll
        for (int r = 0; r < 4; r++) {
            int i = tid + 256*r;
            int qq = i >> 3, seg = i & 7;
            int qa = q0 + qq; if (qa >= NQ) qa = NQ-1;
            pa[r] = *(const float4*)(g_wf + (size_t)qa*KD + c*KC + 4*seg);
        }
#pragma unroll
        for (int r = 0; r < 2; r++) {
            int i = tid + 256*r;
            if (i < BQUADS) {
                int kc = i / NQd, cq = i - kc*NQd;
                pb[r] = *(const float4*)(B + (c*KC + kc)*NN + 4*cq);
            }
        }
    };
    // ---- store chunk helper (regs -> smem buffer) ----
    auto store_chunk = [&](int buf) {
        float* Ab = A_sm + buf*ASZ;
        float* Bb = B_sm + buf*BSZ;
#pragma unroll
        for (int r = 0; r < 4; r++) {
            int i = tid + 256*r;
            int qq = i >> 3, seg = i & 7;
            int shift = 4*seg;                       // 4*((kc>>2)&7), kc = 4*seg+ii
            Ab[(4*seg+0)*RA + shift + qq] = pa[r].x;
            Ab[(4*seg+1)*RA + shift + qq] = pa[r].y;
            Ab[(4*seg+2)*RA + shift + qq] = pa[r].z;
            Ab[(4*seg+3)*RA + shift + qq] = pa[r].w;
        }
#pragma unroll
        for (int r = 0; r < 2; r++) {
            int i = tid + 256*r;
            if (i < BQUADS) {
                int kc = i / NQd, cq = i - kc*NQd;
                *(float4*)(Bb + kc*RB + 4*cq) = pb[r];
            }
        }
    };

    uint64_t acc[4][4];
#pragma unroll
    for (int p = 0; p < 4; p++)
#pragma unroll
        for (int c2 = 0; c2 < 4; c2++) acc[p][c2] = 0ull;

    load_chunk(0);
    store_chunk(0);
    __syncthreads();

    for (int c = 0; c < NCHK; c++) {
        if (c + 1 < NCHK) load_chunk(c + 1);
        const int cur = c & 1;
        const float* Ab = A_sm + cur*ASZ;
        const float* Bb = B_sm + cur*BSZ;

#pragma unroll 8
        for (int kc = 0; kc < KC; kc++) {
            const float* ar = Ab + kc*RA + 4*((kc>>2)&7) + 8*ty;
            ulonglong2 aA = *(const ulonglong2*)ar;        // q pairs (0,1),(2,3)
            ulonglong2 aB = *(const ulonglong2*)(ar + 4);  // q pairs (4,5),(6,7)
            float4 b = *(const float4*)(Bb + kc*RB + 4*txc);
            uint64_t b0 = dup2(b.x), b1 = dup2(b.y), b2 = dup2(b.z), b3 = dup2(b.w);
            acc[0][0] = ffma2(aA.x, b0, acc[0][0]);
            acc[0][1] = ffma2(aA.x, b1, acc[0][1]);
            acc[0][2] = ffma2(aA.x, b2, acc[0][2]);
            acc[0][3] = ffma2(aA.x, b3, acc[0][3]);
            acc[1][0] = ffma2(aA.y, b0, acc[1][0]);
            acc[1][1] = ffma2(aA.y, b1, acc[1][1]);
            acc[1][2] = ffma2(aA.y, b2, acc[1][2]);
            acc[1][3] = ffma2(aA.y, b3, acc[1][3]);
            acc[2][0] = ffma2(aB.x, b0, acc[2][0]);
            acc[2][1] = ffma2(aB.x, b1, acc[2][1]);
            acc[2][2] = ffma2(aB.x, b2, acc[2][2]);
            acc[2][3] = ffma2(aB.x, b3, acc[2][3]);
            acc[3][0] = ffma2(aB.y, b0, acc[3][0]);
            acc[3][1] = ffma2(aB.y, b1, acc[3][1]);
            acc[3][2] = ffma2(aB.y, b2, acc[3][2]);
            acc[3][3] = ffma2(aB.y, b3, acc[3][3]);
        }
        if (c + 1 < NCHK) {
            store_chunk((c + 1) & 1);
            __syncthreads();
        }
    }

    // ---- epilogue ----
    if (NQd != 16 && tx >= NQd) return;   // after all syncs

    float bs[4] = {0.f, 0.f, 0.f, 0.f};
    if (BIAS) {
#pragma unroll
        for (int i = 0; i < 4; i++) {
            int e = 4*tx + i;
            bs[i] = (e < OD) ? bias[e] : 0.0f;
        }
    }

#pragma unroll
    for (int p = 0; p < 4; p++) {
        int qe = q0 + 8*ty + 2*p;
        if (qe < NQ) {
            float4 v = make_float4(lo32(acc[p][0]) + bs[0], lo32(acc[p][1]) + bs[1],
                                   lo32(acc[p][2]) + bs[2], lo32(acc[p][3]) + bs[3]);
            *(float4*)(C + (size_t)qe*NN + 4*tx) = v;
        }
        if (qe + 1 < NQ) {
            float4 v = make_float4(hi32(acc[p][0]) + bs[0], hi32(acc[p][1]) + bs[1],
                                   hi32(acc[p][2]) + bs[2], hi32(acc[p][3]) + bs[3]);
            *(float4*)(C + (size_t)(qe+1)*NN + 4*tx) = v;
        }
    }
}

// ======================= launch =======================
extern "C" void kernel_launch(void* const* d_in, const int* in_sizes, int n_in,
                              void* d_out, int out_size)
{
    const float* qp    = (const float*)d_in[0];
    const float* sp    = (const float*)d_in[1];
    const int*   neigh = (const int*)  d_in[2];
    const float* x     = (const float*)d_in[3];
    const float* kpts  = (const float*)d_in[4];
    const float* ow    = (const float*)d_in[5];
    const float* obias = (const float*)d_in[6];
    const float* w     = (const float*)d_in[7];
    float* out = (float*)d_out;

    static float* s_owpad_ptr = nullptr;
    static float* s_of_ptr    = nullptr;
    if (!s_owpad_ptr) {
        cudaGetSymbolAddress((void**)&s_owpad_ptr, g_owpad);
        cudaGetSymbolAddress((void**)&s_of_ptr,    g_of);
    }

    constexpr int SM48 = (2*KC*RA + 2*KC*(48+4)) * 4;
    constexpr int SM64 = (2*KC*RA + 2*KC*(64+4)) * 4;
    cudaFuncSetAttribute(gemm_kernel<48, true>,
                         cudaFuncAttributeMaxDynamicSharedMemorySize, SM48);
    cudaFuncSetAttribute(gemm_kernel<64, false>,
                         cudaFuncAttributeMaxDynamicSharedMemorySize, SM64);

    prep_owpad<<<(KD*ODP + 255)/256, 256>>>(ow);

    // K1: rigid aggregation -> WF1 (g_wf)
    agg_kernel<false><<<NQ/8, 256>>>(qp, sp, neigh, x, kpts);

    // K2: offset GEMM (+bias) -> g_of
    gemm_kernel<48, true><<<GEMM_BLOCKS, 256, SM48>>>(s_owpad_ptr, obias, s_of_ptr);

    // K3: deformed aggregation -> WF2 (g_wf, reused)
    agg_kernel<true><<<NQ/8, 256>>>(qp, sp, neigh, x, kpts);

    // K4: output GEMM -> out
    gemm_kernel<64, false><<<GEMM_BLOCKS, 256, SM64>>>(w, nullptr, out);
}